// round 17
// baseline (speedup 1.0000x reference)
#include <cuda_runtime.h>
#include <cuda_fp16.h>
#include <cstdint>
#include <math.h>

#define NT 8192
#define DM 2048
#define DH 2048
#define NE 16

#define BM 128
#define BN 256
#define BK 64                   // 64 halves deep
#define KTILES (DM / BK)        // 32
#define NSTAGE 4
#define THREADS 512

#define A_BYTES 16384           // 128 m-rows * 128 B (k-major, swizzled)
#define B_BYTES 32768           // 64 k-rows * 512 B (n-major, swizzled)
#define STAGE_BYTES (A_BYTES + B_BYTES)         // 48 KB
#define SMEM_BYTES (NSTAGE * STAGE_BYTES + 1024)

#define ROUTER_BLOCKS (NT / 8)                  // 1024 blocks, 8 warps each
#define CONVERT_BLOCKS ((NE * DM * DH / 8) / 256)   // 32768

#define SWZ(o) ((unsigned)(o) ^ ((((unsigned)(o)) >> 3) & 0x70))

// ---------------- device scratch (allocation-free) ----------------
__device__ int    g_count[NE];
__device__ int    g_list[NE][NT];                   // token*2 + slot
__device__ float  g_gate[NE][NT];
__device__ float  g_scratch[(size_t)NT * 2 * DH];   // 128 MB combine scratch
__device__ __half g_xh[(size_t)NT * DM];            // 32 MB  fp16 x
__device__ __half g_wh[(size_t)NE * DM * DH];       // 128 MB fp16 W, original [e][k][n]

// ---------------- helpers ----------------
__device__ __forceinline__ uint32_t smem_u32(const void* p) {
    return (uint32_t)__cvta_generic_to_shared(p);
}
__device__ __forceinline__ unsigned h2_bits(__half2 h) {
    __half2_raw r = *reinterpret_cast<__half2_raw*>(&h);
    return ((unsigned)r.y << 16) | (unsigned)r.x;
}
__device__ __forceinline__ void mma_f16(float& c0, float& c1, float& c2, float& c3,
                                        unsigned a0, unsigned a1, unsigned a2, unsigned a3,
                                        unsigned b0, unsigned b1) {
    asm volatile(
        "mma.sync.aligned.m16n8k16.row.col.f32.f16.f16.f32 "
        "{%0,%1,%2,%3}, {%4,%5,%6,%7}, {%8,%9}, {%0,%1,%2,%3};"
        : "+f"(c0), "+f"(c1), "+f"(c2), "+f"(c3)
        : "r"(a0), "r"(a1), "r"(a2), "r"(a3), "r"(b0), "r"(b1));
}
#define LDSM_X4(r0, r1, r2, r3, addr)                                        \
    asm volatile("ldmatrix.sync.aligned.m8n8.x4.shared.b16 {%0,%1,%2,%3}, [%4];" \
        : "=r"(r0), "=r"(r1), "=r"(r2), "=r"(r3) : "r"(addr))
#define LDSM_X4_T(r0, r1, r2, r3, addr)                                      \
    asm volatile("ldmatrix.sync.aligned.m8n8.x4.trans.shared.b16 {%0,%1,%2,%3}, [%4];" \
        : "=r"(r0), "=r"(r1), "=r"(r2), "=r"(r3) : "r"(addr))

#define CP_ASYNC16(dst, src) \
    asm volatile("cp.async.cg.shared.global [%0], [%1], 16;" :: "r"(dst), "l"(src))
#define CP_COMMIT()  asm volatile("cp.async.commit_group;" ::)
#define CP_WAIT(n)   asm volatile("cp.async.wait_group %0;" :: "n"(n))

// ---------------------------------------------------------------------------
__global__ void zero_counters() {
    if (threadIdx.x < NE) g_count[threadIdx.x] = 0;
}

// ---------------------------------------------------------------------------
// Fused prep: router blocks [0, ROUTER_BLOCKS) start in wave 0 and overlap
// with the W fp32->fp16 streaming convert (remaining blocks).
// ---------------------------------------------------------------------------
__global__ void prep_kernel(const float4* __restrict__ w,
                            const float* __restrict__ x,
                            const float* __restrict__ rw) {
    if (blockIdx.x < ROUTER_BLOCKS) {
        // ---- router: warp per token; also writes fp16 x copy ----
        int token = blockIdx.x * 8 + (threadIdx.x >> 5);
        int lane  = threadIdx.x & 31;

        const float* xr = x + (size_t)token * DM;
        __half* xo = g_xh + (size_t)token * DM;
        float acc[NE];
#pragma unroll
        for (int e = 0; e < NE; e++) acc[e] = 0.f;

        for (int i = lane; i < DM; i += 32) {
            float xv = xr[i];
            xo[i] = __float2half_rn(xv);
#pragma unroll
            for (int e = 0; e < NE; e++)
                acc[e] = fmaf(xv, rw[e * DM + i], acc[e]);
        }
#pragma unroll
        for (int off = 16; off > 0; off >>= 1) {
#pragma unroll
            for (int e = 0; e < NE; e++)
                acc[e] += __shfl_xor_sync(0xFFFFFFFFu, acc[e], off);
        }

        if (lane == 0) {
            int i1 = 0; float v1 = acc[0];
#pragma unroll
            for (int e = 1; e < NE; e++)
                if (acc[e] > v1) { v1 = acc[e]; i1 = e; }
            int i2 = -1; float v2 = -3.402823466e38f;
#pragma unroll
            for (int e = 0; e < NE; e++)
                if (e != i1 && acc[e] > v2) { v2 = acc[e]; i2 = e; }

            float t  = expf(v2 - v1);
            float g1 = 1.f / (1.f + t);
            float g2 = t * g1;

            int p1 = atomicAdd(&g_count[i1], 1);
            g_list[i1][p1] = token * 2 + 0; g_gate[i1][p1] = g1;
            int p2 = atomicAdd(&g_count[i2], 1);
            g_list[i2][p2] = token * 2 + 1; g_gate[i2][p2] = g2;
        }
    } else {
        // ---- streaming W convert (layout preserved) ----
        size_t i = (size_t)(blockIdx.x - ROUTER_BLOCKS) * blockDim.x + threadIdx.x;
        float4 v0 = w[2 * i];
        float4 v1 = w[2 * i + 1];
        uint4 p;
        p.x = h2_bits(__float22half2_rn(make_float2(v0.x, v0.y)));
        p.y = h2_bits(__float22half2_rn(make_float2(v0.z, v0.w)));
        p.z = h2_bits(__float22half2_rn(make_float2(v1.x, v1.y)));
        p.w = h2_bits(__float22half2_rn(make_float2(v1.z, v1.w)));
        reinterpret_cast<uint4*>(g_wh)[i] = p;
    }
}

// ---------------------------------------------------------------------------
// Gathered per-expert GEMM: CTA 128x256, 16 warps, warp tile 32x64,
// fp16 m16n8k16, 4-stage cp.async, cross-tile fragment prefetch
// (LDSM for step g+1 always precedes MMA(g), including across kt boundary).
// ---------------------------------------------------------------------------
__global__ void __launch_bounds__(THREADS, 1)
moe_gemm_kernel() {
    extern __shared__ char dyn[];
    const uint32_t sbase = (smem_u32(dyn) + 1023u) & ~1023u;

    const int e   = blockIdx.z;
    const int cnt = g_count[e];
    const int m0  = blockIdx.y * BM;
    if (m0 >= cnt) return;
    const int n0  = blockIdx.x * BN;

    const int tid  = threadIdx.x;
    const int lane = tid & 31;
    const int wid  = tid >> 5;
    const int wm   = wid & 3;     // 4 warp-rows (32 M each)
    const int wn   = wid >> 2;    // 4 warp-cols (64 N each)
    const int grp  = lane >> 2;
    const int tg   = lane & 3;

    // ---- A cp.async: 2 chunks/thread, [m][k] 128B rows, SWZ ----
    const int rrA  = tid >> 3;            // 0..63
    const int cc8  = tid & 7;
    const __half* aSrc[2];
#pragma unroll
    for (int i = 0; i < 2; i++) {
        int gm = m0 + rrA + 64 * i; if (gm >= cnt) gm = cnt - 1;
        int tok = g_list[e][gm] >> 1;
        aSrc[i] = g_xh + (size_t)tok * DM + cc8 * 8;
    }
    const uint32_t aOff0 = SWZ(rrA * 128 + cc8 * 16);

    // ---- B cp.async: 4 chunks/thread, [k][n] 512B rows ----
    const int kB  = tid >> 5;             // 0..15
    const int ciB = tid & 31;
    const __half* bSrc0 = g_wh + ((size_t)e * DM + kB) * DH + n0 + ciB * 8;
    const uint32_t bOff0 = (uint32_t)(kB * 512 + ciB * 16) ^ (((uint32_t)kB & 7) << 4);

#define LOAD_STAGE(s, kt)                                                    \
    do {                                                                     \
        uint32_t _b = sbase + (uint32_t)(s) * STAGE_BYTES;                   \
        _Pragma("unroll")                                                    \
        for (int i = 0; i < 2; i++)                                          \
            CP_ASYNC16(_b + aOff0 + i * 8192u, aSrc[i] + (kt) * BK);         \
        _Pragma("unroll")                                                    \
        for (int i = 0; i < 4; i++)                                          \
            CP_ASYNC16(_b + A_BYTES + bOff0 + i * 8192u,                     \
                       bSrc0 + ((size_t)(kt) * BK + i * 16) * DH);           \
        CP_COMMIT();                                                         \
    } while (0)

    LOAD_STAGE(0, 0);
    LOAD_STAGE(1, 1);
    LOAD_STAGE(2, 2);

    // ---- A ldmatrix geometry (warp tile 32 M) ----
    const uint32_t key = lane & 7;
    const uint32_t aRB = (uint32_t)(wm * 32 + ((lane >> 3) & 1) * 8 + (lane & 7)) * 128;
    const uint32_t aCH = (lane >> 4) & 1;

    // ---- B ldmatrix.trans geometry (warp tile 64 N) ----
    const uint32_t mat  = lane >> 3;
    const uint32_t k_r  = (mat & 1) * 8 + (lane & 7);
    const uint32_t n_b  = (uint32_t)(wn * 64) + (mat >> 1) * 8;
    const uint32_t bBase = k_r * 512 + n_b * 2;
    const uint32_t bXOR  = (k_r & 7) << 4;

    float c[2][8][4];
#pragma unroll
    for (int mb = 0; mb < 2; mb++)
#pragma unroll
        for (int nb = 0; nb < 8; nb++)
#pragma unroll
            for (int j = 0; j < 4; j++) c[mb][nb][j] = 0.f;

    unsigned af[2][2][4];   // [buf][mb][frag]
    unsigned bf[2][4][4];   // [buf][nb2][frag]

#define LOAD_FRAGS(buf, sA, sB, ks)                                          \
    do {                                                                     \
        const uint32_t _ca = (((ks) * 2 + aCH) ^ key) << 4;                  \
        _Pragma("unroll")                                                    \
        for (int mb = 0; mb < 2; mb++)                                       \
            LDSM_X4(af[buf][mb][0], af[buf][mb][1], af[buf][mb][2],          \
                    af[buf][mb][3], (sA) + aRB + mb * 2048u + _ca);          \
        _Pragma("unroll")                                                    \
        for (int nb2 = 0; nb2 < 4; nb2++)                                    \
            LDSM_X4_T(bf[buf][nb2][0], bf[buf][nb2][1], bf[buf][nb2][2],     \
                      bf[buf][nb2][3],                                       \
                      (sB) + ((bBase + (ks) * 8192u + nb2 * 32u) ^ bXOR));   \
    } while (0)

#define MMA_FRAGS(buf)                                                       \
    do {                                                                     \
        _Pragma("unroll")                                                    \
        for (int mb = 0; mb < 2; mb++)                                       \
            _Pragma("unroll")                                                \
            for (int nb = 0; nb < 8; nb++) {                                 \
                const unsigned b0 = bf[buf][nb >> 1][(nb & 1) * 2];          \
                const unsigned b1 = bf[buf][nb >> 1][(nb & 1) * 2 + 1];     \
                mma_f16(c[mb][nb][0], c[mb][nb][1], c[mb][nb][2],            \
                        c[mb][nb][3], af[buf][mb][0], af[buf][mb][1],        \
                        af[buf][mb][2], af[buf][mb][3], b0, b1);             \
            }                                                                \
    } while (0)

    // Prologue: ensure stage 0 landed (3 commits outstanding -> wait<=2 lands #0,#1)
    CP_WAIT(2);
    __syncthreads();
    {
        const uint32_t sA0 = sbase;
        const uint32_t sB0 = sA0 + A_BYTES;
        LOAD_FRAGS(0, sA0, sB0, 0);
    }

    for (int kt = 0; kt < KTILES; kt++) {
        const uint32_t sA  = sbase + (uint32_t)(kt & 3) * STAGE_BYTES;
        const uint32_t sB  = sA + A_BYTES;
        const uint32_t sAn = sbase + (uint32_t)((kt + 1) & 3) * STAGE_BYTES;
        const uint32_t sBn = sAn + A_BYTES;

#pragma unroll
        for (int ks = 0; ks < 4; ks++) {
            if (ks < 3) {
                LOAD_FRAGS((ks + 1) & 1, sA, sB, ks + 1);
            } else if (kt + 1 < KTILES) {
                // cross-tile prefetch: stage kt+1 is guaranteed landed
                LOAD_FRAGS(0, sAn, sBn, 0);
            }
            MMA_FRAGS(ks & 1);
        }

        if (kt + 1 < KTILES) {
            // bottom-of-tile: tightened wait guarantees stage kt+2 landed here,
            // which keeps the NEXT iteration's cross-tile prefetch safe.
            if (kt < KTILES - 3) CP_WAIT(1);
            else                 CP_WAIT(0);
            __syncthreads();
            if (kt + 3 < KTILES) LOAD_STAGE((kt + 3) & 3, kt + 3);
        }
    }
#undef LOAD_STAGE
#undef LOAD_FRAGS
#undef MMA_FRAGS

    // ---- epilogue: gate-scale, STG.64 into disjoint (token,slot) scratch rows ----
#pragma unroll
    for (int mb = 0; mb < 2; mb++) {
#pragma unroll
        for (int half = 0; half < 2; half++) {
            int gm = m0 + wm * 32 + mb * 16 + grp + half * 8;
            if (gm >= cnt) continue;
            int   sl = g_list[e][gm];
            float gt = g_gate[e][gm];
            float* orow = g_scratch + (size_t)sl * DH + n0 + wn * 64;
#pragma unroll
            for (int nb = 0; nb < 8; nb++) {
                int col = nb * 8 + 2 * tg;
                float2 v = make_float2(gt * c[mb][nb][half * 2 + 0],
                                       gt * c[mb][nb][half * 2 + 1]);
                *reinterpret_cast<float2*>(orow + col) = v;
            }
        }
    }
}

// ---------------------------------------------------------------------------
// Combine: out[t] = scratch[2t] + scratch[2t+1]
// ---------------------------------------------------------------------------
__global__ void combine_kernel(float4* __restrict__ out) {
    const int C = DH / 4;
    int i = blockIdx.x * blockDim.x + threadIdx.x;
    int t = i / C, col = i - t * C;
    const float4* s = reinterpret_cast<const float4*>(g_scratch);
    float4 a = s[(size_t)(2 * t) * C + col];
    float4 b = s[(size_t)(2 * t + 1) * C + col];
    out[i] = make_float4(a.x + b.x, a.y + b.y, a.z + b.z, a.w + b.w);
}

// ---------------------------------------------------------------------------
extern "C" void kernel_launch(void* const* d_in, const int* in_sizes, int n_in,
                              void* d_out, int out_size) {
    const float* x  = (const float*)d_in[0];   // [NT, DM]
    const float* rw = (const float*)d_in[1];   // [NE, DM]
    const float* ew = (const float*)d_in[2];   // [NE, DM, DH]
    float* out = (float*)d_out;                // [NT, DH]

    cudaFuncSetAttribute(moe_gemm_kernel,
                         cudaFuncAttributeMaxDynamicSharedMemorySize, SMEM_BYTES);

    zero_counters<<<1, 32>>>();
    prep_kernel<<<ROUTER_BLOCKS + CONVERT_BLOCKS, 256>>>((const float4*)ew, x, rw);

    dim3 grid(DH / BN, NT / BM, NE);           // (8, 64, 16), early-exit on cnt
    moe_gemm_kernel<<<grid, THREADS, SMEM_BYTES>>>();

    combine_kernel<<<(NT * DH / 4) / 256, 256>>>((float4*)out);
}